// round 4
// baseline (speedup 1.0000x reference)
#include <cuda_runtime.h>

#define NN 50000
#define EE 800000
#define CC 128
#define HH 4

// ---------------- device scratch (static: no allocations allowed) ----------
__device__ float g_h[NN * CC];        // GEMM output (h) per layer
__device__ float g_xbuf[NN * CC];     // layer-0 output / layer-1 input
__device__ float g_ssrc[NN * HH];     // per-node src scores
__device__ float g_sdst[NN * HH];     // per-node dst scores
__device__ int   g_counts[NN];
__device__ int   g_rowptr[NN + 1];
__device__ int   g_fill[NN];
__device__ int   g_esrc[EE];          // CSR-ordered src index
__device__ float g_ewq[EE];           // CSR-ordered edge weight
__device__ int   g_ewmax_bits;
__device__ float g_cedge[2][HH];

__device__ __forceinline__ float lrelu_att(float v) { return fmaxf(v, 0.2f * v); }

// ---------------- setup kernels -------------------------------------------
__global__ void init_kernel() {
    int i = blockIdx.x * blockDim.x + threadIdx.x;
    if (i == 0) g_ewmax_bits = 0;
    for (; i < NN; i += gridDim.x * blockDim.x) g_counts[i] = 0;
}

__global__ void ewmax_kernel(const float* __restrict__ ew) {
    float m = 0.f;
    for (int i = blockIdx.x * blockDim.x + threadIdx.x; i < EE; i += gridDim.x * blockDim.x)
        m = fmaxf(m, ew[i]);
    #pragma unroll
    for (int o = 16; o; o >>= 1) m = fmaxf(m, __shfl_xor_sync(~0u, m, o));
    if ((threadIdx.x & 31) == 0) atomicMax(&g_ewmax_bits, __float_as_int(m));
}

__global__ void count_kernel(const int* __restrict__ ei) {
    for (int e = blockIdx.x * blockDim.x + threadIdx.x; e < EE; e += gridDim.x * blockDim.x)
        atomicAdd(&g_counts[ei[EE + e]], 1);
}

__global__ void scan_kernel() {
    __shared__ int partials[1024];
    int t = threadIdx.x;
    const int CH = (NN + 1023) / 1024;
    int beg = t * CH;
    int end = beg + CH; if (end > NN) end = NN;
    int s = 0;
    for (int i = beg; i < end; i++) s += g_counts[i];
    partials[t] = s;
    __syncthreads();
    for (int off = 1; off < 1024; off <<= 1) {
        int v = (t >= off) ? partials[t - off] : 0;
        __syncthreads();
        partials[t] += v;
        __syncthreads();
    }
    int run = (t == 0) ? 0 : partials[t - 1];
    for (int i = beg; i < end; i++) {
        g_rowptr[i] = run;
        g_fill[i] = run;
        run += g_counts[i];
    }
    if (t == 1023) g_rowptr[NN] = partials[1023];
}

__global__ void scatter_kernel(const int* __restrict__ ei, const float* __restrict__ ew) {
    for (int e = blockIdx.x * blockDim.x + threadIdx.x; e < EE; e += gridDim.x * blockDim.x) {
        int d = ei[EE + e];
        int pos = atomicAdd(&g_fill[d], 1);
        g_esrc[pos] = ei[e];
        g_ewq[pos]  = ew[e];
    }
}

// c[h] = sum_d We[h*32+d] * a_edge[h*32+d]  (edge embedding collapses to a scalar/head)
__global__ void cedge_kernel(const float* __restrict__ We0, const float* __restrict__ ae0,
                             const float* __restrict__ We1, const float* __restrict__ ae1) {
    const float* We = blockIdx.x ? We1 : We0;
    const float* ae = blockIdx.x ? ae1 : ae0;
    int t = threadIdx.x;
    float p = We[t] * ae[t];
    #pragma unroll
    for (int o = 16; o; o >>= 1) p += __shfl_xor_sync(~0u, p, o);
    if ((t & 31) == 0) g_cedge[blockIdx.x][t >> 5] = p;
}

// ---------------- fused GroupNorm + LeakyReLU + GEMM + scores -------------
// Block = 128 threads, 32 rows/block. Warp w owns rows {w, w+4, ..., w+28};
// lane l owns cols [4l, 4l+4). Per k: 1 LDS.128 (W) + 8 broadcasts vs 32 FFMA.
__global__ void __launch_bounds__(128) gemm_kernel(
    const float* __restrict__ x, const float* __restrict__ gamma, const float* __restrict__ beta,
    const float* __restrict__ W, const float* __restrict__ a_src, const float* __restrict__ a_dst,
    float* __restrict__ hout, float* __restrict__ ssrc, float* __restrict__ sdst)
{
    extern __shared__ float sh[];
    float* Wsh = sh;            // 128*128
    float* xs  = sh + 16384;    // 32*128
    int t = threadIdx.x, w = t >> 5, l = t & 31;
    int row0 = blockIdx.x * 32;

    for (int i = t; i < 16384; i += 128) Wsh[i] = W[i];

    float4 gmm = reinterpret_cast<const float4*>(gamma)[l];
    float4 bt  = reinterpret_cast<const float4*>(beta)[l];
    float4 a_s = reinterpret_cast<const float4*>(a_src)[l];
    float4 a_d = reinterpret_cast<const float4*>(a_dst)[l];

    // norm + activation: lane's 4 channels all lie in one 16-channel group (group = l/4)
    #pragma unroll
    for (int j = 0; j < 8; j++) {
        int rl = w + 4 * j;
        int row = row0 + rl;
        float4 v = make_float4(0.f, 0.f, 0.f, 0.f);
        if (row < NN) v = reinterpret_cast<const float4*>(x)[row * 32 + l];
        float s1 = v.x + v.y + v.z + v.w;
        float s2 = v.x * v.x + v.y * v.y + v.z * v.z + v.w * v.w;
        s1 += __shfl_xor_sync(~0u, s1, 1, 4); s2 += __shfl_xor_sync(~0u, s2, 1, 4);
        s1 += __shfl_xor_sync(~0u, s1, 2, 4); s2 += __shfl_xor_sync(~0u, s2, 2, 4);
        float mu  = s1 * (1.f / 16.f);
        float var = s2 * (1.f / 16.f) - mu * mu;
        float rs  = rsqrtf(var + 1e-5f);
        float4 xn;
        xn.x = (v.x - mu) * rs * gmm.x + bt.x;
        xn.y = (v.y - mu) * rs * gmm.y + bt.y;
        xn.z = (v.z - mu) * rs * gmm.z + bt.z;
        xn.w = (v.w - mu) * rs * gmm.w + bt.w;
        xn.x = fmaxf(xn.x, 0.01f * xn.x);
        xn.y = fmaxf(xn.y, 0.01f * xn.y);
        xn.z = fmaxf(xn.z, 0.01f * xn.z);
        xn.w = fmaxf(xn.w, 0.01f * xn.w);
        reinterpret_cast<float4*>(xs)[rl * 32 + l] = xn;
    }
    __syncthreads();

    float4 acc[8];
    #pragma unroll
    for (int j = 0; j < 8; j++) acc[j] = make_float4(0.f, 0.f, 0.f, 0.f);
    const float4* W4 = reinterpret_cast<const float4*>(Wsh);
    #pragma unroll 4
    for (int k = 0; k < 128; k++) {
        float4 wv = W4[k * 32 + l];
        #pragma unroll
        for (int j = 0; j < 8; j++) {
            float xk = xs[(w + 4 * j) * 128 + k];
            acc[j].x += wv.x * xk;
            acc[j].y += wv.y * xk;
            acc[j].z += wv.z * xk;
            acc[j].w += wv.w * xk;
        }
    }

    // epilogue: store h + per-head score dots (head = l/8; reduce over 8 lanes)
    #pragma unroll
    for (int j = 0; j < 8; j++) {
        int row = row0 + w + 4 * j;
        if (row < NN) {
            reinterpret_cast<float4*>(hout)[row * 32 + l] = acc[j];
            float ps = acc[j].x * a_s.x + acc[j].y * a_s.y + acc[j].z * a_s.z + acc[j].w * a_s.w;
            float pd = acc[j].x * a_d.x + acc[j].y * a_d.y + acc[j].z * a_d.z + acc[j].w * a_d.w;
            ps += __shfl_xor_sync(~0u, ps, 1, 8); pd += __shfl_xor_sync(~0u, pd, 1, 8);
            ps += __shfl_xor_sync(~0u, ps, 2, 8); pd += __shfl_xor_sync(~0u, pd, 2, 8);
            ps += __shfl_xor_sync(~0u, ps, 4, 8); pd += __shfl_xor_sync(~0u, pd, 4, 8);
            if ((l & 7) == 0) {
                ssrc[row * 4 + (l >> 3)] = ps;
                sdst[row * 4 + (l >> 3)] = pd;
            }
        }
    }
}

// ---------------- per-dst softmax + aggregation (1 warp / node) ------------
__global__ void __launch_bounds__(256) aggr_kernel(
    const float* __restrict__ hmat, const float* __restrict__ ssrc, const float* __restrict__ sdst,
    const float* __restrict__ bias, float* __restrict__ out, int layer)
{
    __shared__ int    sh_src[8][32];
    __shared__ float4 sh_w[8][32];
    int wid = threadIdx.x >> 5, l = threadIdx.x & 31;
    int n = blockIdx.x * 8 + wid;
    if (n >= NN) return;

    int beg = g_rowptr[n], end = g_rowptr[n + 1];
    float c0 = g_cedge[layer][0], c1 = g_cedge[layer][1];
    float c2 = g_cedge[layer][2], c3 = g_cedge[layer][3];
    float ewm = __int_as_float(g_ewmax_bits);
    float4 sd  = reinterpret_cast<const float4*>(sdst)[n];
    float4 ssn = reinterpret_cast<const float4*>(ssrc)[n];

    // self-loop logits
    float ls0 = lrelu_att(ssn.x + sd.x + ewm * c0);
    float ls1 = lrelu_att(ssn.y + sd.y + ewm * c1);
    float ls2 = lrelu_att(ssn.z + sd.z + ewm * c2);
    float ls3 = lrelu_att(ssn.w + sd.w + ewm * c3);

    // pass 1: per-head max over in-edges
    float M0 = ls0, M1 = ls1, M2 = ls2, M3 = ls3;
    for (int e = beg + l; e < end; e += 32) {
        int s = g_esrc[e];
        float wg = g_ewq[e];
        float4 ss = reinterpret_cast<const float4*>(ssrc)[s];
        M0 = fmaxf(M0, lrelu_att(ss.x + sd.x + wg * c0));
        M1 = fmaxf(M1, lrelu_att(ss.y + sd.y + wg * c1));
        M2 = fmaxf(M2, lrelu_att(ss.z + sd.z + wg * c2));
        M3 = fmaxf(M3, lrelu_att(ss.w + sd.w + wg * c3));
    }
    #pragma unroll
    for (int o = 16; o; o >>= 1) {
        M0 = fmaxf(M0, __shfl_xor_sync(~0u, M0, o));
        M1 = fmaxf(M1, __shfl_xor_sync(~0u, M1, o));
        M2 = fmaxf(M2, __shfl_xor_sync(~0u, M2, o));
        M3 = fmaxf(M3, __shfl_xor_sync(~0u, M3, o));
    }

    float w0s = __expf(ls0 - M0), w1s = __expf(ls1 - M1);
    float w2s = __expf(ls2 - M2), w3s = __expf(ls3 - M3);

    const float* hn = hmat + n * 128 + l;
    float acc0 = w0s * hn[0];
    float acc1 = w1s * hn[32];
    float acc2 = w2s * hn[64];
    float acc3 = w3s * hn[96];
    float sum0 = 0.f, sum1 = 0.f, sum2 = 0.f, sum3 = 0.f;

    // pass 2: chunks of 32 edges: lane-parallel exp (phase A), warp-serial
    // feature accumulation (phase B — 4x128B coalesced gathers/edge, L2-resident h)
    for (int base = beg; base < end; base += 32) {
        int e = base + l;
        if (e < end) {
            int s = g_esrc[e];
            float wg = g_ewq[e];
            float4 ss = reinterpret_cast<const float4*>(ssrc)[s];
            float e0 = __expf(lrelu_att(ss.x + sd.x + wg * c0) - M0);
            float e1 = __expf(lrelu_att(ss.y + sd.y + wg * c1) - M1);
            float e2 = __expf(lrelu_att(ss.z + sd.z + wg * c2) - M2);
            float e3 = __expf(lrelu_att(ss.w + sd.w + wg * c3) - M3);
            sum0 += e0; sum1 += e1; sum2 += e2; sum3 += e3;
            sh_src[wid][l] = s;
            sh_w[wid][l] = make_float4(e0, e1, e2, e3);
        }
        __syncwarp();
        int cnt = end - base; if (cnt > 32) cnt = 32;
        for (int i = 0; i < cnt; i++) {
            int s = sh_src[wid][i];
            float4 wv = sh_w[wid][i];
            const float* hp = hmat + s * 128 + l;
            acc0 += wv.x * hp[0];
            acc1 += wv.y * hp[32];
            acc2 += wv.z * hp[64];
            acc3 += wv.w * hp[96];
        }
        __syncwarp();
    }

    #pragma unroll
    for (int o = 16; o; o >>= 1) {
        sum0 += __shfl_xor_sync(~0u, sum0, o);
        sum1 += __shfl_xor_sync(~0u, sum1, o);
        sum2 += __shfl_xor_sync(~0u, sum2, o);
        sum3 += __shfl_xor_sync(~0u, sum3, o);
    }
    sum0 += w0s; sum1 += w1s; sum2 += w2s; sum3 += w3s;
    float i0 = 1.f / (sum0 + 1e-16f), i1 = 1.f / (sum1 + 1e-16f);
    float i2 = 1.f / (sum2 + 1e-16f), i3 = 1.f / (sum3 + 1e-16f);

    float* op = out + n * 128 + l;
    op[0]  = acc0 * i0 + bias[l];
    op[32] = acc1 * i1 + bias[32 + l];
    op[64] = acc2 * i2 + bias[64 + l];
    op[96] = acc3 * i3 + bias[96 + l];
}

// ---------------- launch ---------------------------------------------------
extern "C" void kernel_launch(void* const* d_in, const int* in_sizes, int n_in,
                              void* d_out, int out_size) {
    const float* x  = (const float*)d_in[0];
    const int*   ei = (const int*)d_in[1];
    const float* ew = (const float*)d_in[2];
    const float* P[2][8];
    for (int L = 0; L < 2; L++)
        for (int j = 0; j < 8; j++)
            P[L][j] = (const float*)d_in[3 + L * 8 + j];
    // P[L]: 0 gamma, 1 beta, 2 W, 3 We, 4 a_src, 5 a_dst, 6 a_edge, 7 bias

    float *d_h, *d_xbuf, *d_ssrc, *d_sdst;
    cudaGetSymbolAddress((void**)&d_h,    g_h);
    cudaGetSymbolAddress((void**)&d_xbuf, g_xbuf);
    cudaGetSymbolAddress((void**)&d_ssrc, g_ssrc);
    cudaGetSymbolAddress((void**)&d_sdst, g_sdst);

    cudaFuncSetAttribute(gemm_kernel, cudaFuncAttributeMaxDynamicSharedMemorySize, 81920);

    // graph preprocessing (same every call — deterministic work)
    init_kernel<<<128, 256>>>();
    ewmax_kernel<<<256, 256>>>(ew);
    count_kernel<<<512, 256>>>(ei);
    scan_kernel<<<1, 1024>>>();
    scatter_kernel<<<512, 256>>>(ei, ew);
    cedge_kernel<<<2, 128>>>(P[0][3], P[0][6], P[1][3], P[1][6]);

    const int gemm_blocks = (NN + 31) / 32;
    const int aggr_blocks = (NN + 7) / 8;

    // layer 0
    gemm_kernel<<<gemm_blocks, 128, 81920>>>(x, P[0][0], P[0][1], P[0][2], P[0][4], P[0][5],
                                             d_h, d_ssrc, d_sdst);
    aggr_kernel<<<aggr_blocks, 256>>>(d_h, d_ssrc, d_sdst, P[0][7], d_xbuf, 0);

    // layer 1
    gemm_kernel<<<gemm_blocks, 128, 81920>>>(d_xbuf, P[1][0], P[1][1], P[1][2], P[1][4], P[1][5],
                                             d_h, d_ssrc, d_sdst);
    aggr_kernel<<<aggr_blocks, 256>>>(d_h, d_ssrc, d_sdst, P[1][7], (float*)d_out, 1);
}

// round 7
// speedup vs baseline: 1.2234x; 1.2234x over previous
#include <cuda_runtime.h>

#define NN 50000
#define EE 800000
#define CC 128
#define HH 4
#define SCAN_B 196   // 196 * 256 = 50176 >= NN

// ---------------- device scratch (static: no allocations allowed) ----------
__device__ float g_h[NN * CC];        // GEMM output (h) per layer
__device__ float g_xbuf[NN * CC];     // layer-0 output / layer-1 input
__device__ float g_ssrc[NN * HH];     // per-node src scores
__device__ float g_sdst[NN * HH];     // per-node dst scores
__device__ int   g_counts[NN];
__device__ int   g_rowptr[NN + 1];
__device__ int   g_fill[NN];
__device__ int   g_esrc[EE];          // CSR-ordered src index
__device__ float g_ewq[EE];           // CSR-ordered edge weight
__device__ int   g_part[SCAN_B];      // per-block count sums
__device__ int   g_partscan[SCAN_B];  // exclusive scan of g_part
__device__ int   g_ewmax_bits;
__device__ float g_cedge[2][HH];

__device__ __forceinline__ float lrelu_att(float v) { return fmaxf(v, 0.2f * v); }

// ---------------- setup kernels -------------------------------------------
// zero counts + reduce max edge weight, one kernel
__global__ void init_ewmax_kernel(const float* __restrict__ ew) {
    int i = blockIdx.x * blockDim.x + threadIdx.x;
    int stride = gridDim.x * blockDim.x;
    if (i == 0) g_ewmax_bits = 0;
    for (int j = i; j < NN; j += stride) g_counts[j] = 0;
    float m = 0.f;
    for (int j = i; j < EE; j += stride) m = fmaxf(m, ew[j]);
    #pragma unroll
    for (int o = 16; o; o >>= 1) m = fmaxf(m, __shfl_xor_sync(~0u, m, o));
    if ((threadIdx.x & 31) == 0) atomicMax(&g_ewmax_bits, __float_as_int(m));
}

__global__ void count_kernel(const int* __restrict__ ei) {
    for (int e = blockIdx.x * blockDim.x + threadIdx.x; e < EE; e += gridDim.x * blockDim.x)
        atomicAdd(&g_counts[ei[EE + e]], 1);
}

// --- 3-phase parallel scan over g_counts ---
__global__ void __launch_bounds__(256) scanA_kernel() {   // per-block sums
    __shared__ int wsum[8];
    int i = blockIdx.x * 256 + threadIdx.x;
    int v = (i < NN) ? g_counts[i] : 0;
    int s = v;
    #pragma unroll
    for (int o = 16; o; o >>= 1) s += __shfl_xor_sync(~0u, s, o);
    if ((threadIdx.x & 31) == 0) wsum[threadIdx.x >> 5] = s;
    __syncthreads();
    if (threadIdx.x < 8) {
        int t = wsum[threadIdx.x];
        #pragma unroll
        for (int o = 4; o; o >>= 1) t += __shfl_xor_sync(0xff, t, o);
        if (threadIdx.x == 0) g_part[blockIdx.x] = t;
    }
}

__global__ void __launch_bounds__(256) scanB_kernel() {   // scan the 196 partials
    __shared__ int a[256];
    int t = threadIdx.x;
    int v = (t < SCAN_B) ? g_part[t] : 0;
    a[t] = v;
    __syncthreads();
    #pragma unroll
    for (int off = 1; off < 256; off <<= 1) {
        int x = (t >= off) ? a[t - off] : 0;
        __syncthreads();
        a[t] += x;
        __syncthreads();
    }
    if (t < SCAN_B) g_partscan[t] = a[t] - v;   // exclusive
    if (t == SCAN_B - 1) g_rowptr[NN] = a[t];   // total
}

__global__ void __launch_bounds__(256) scanC_kernel() {   // local scan + writeback
    __shared__ int a[256];
    int t = threadIdx.x;
    int i = blockIdx.x * 256 + t;
    int v = (i < NN) ? g_counts[i] : 0;
    a[t] = v;
    __syncthreads();
    #pragma unroll
    for (int off = 1; off < 256; off <<= 1) {
        int x = (t >= off) ? a[t - off] : 0;
        __syncthreads();
        a[t] += x;
        __syncthreads();
    }
    if (i < NN) {
        int r = g_partscan[blockIdx.x] + a[t] - v;
        g_rowptr[i] = r;
        g_fill[i]   = r;
    }
}

__global__ void scatter_kernel(const int* __restrict__ ei, const float* __restrict__ ew) {
    for (int e = blockIdx.x * blockDim.x + threadIdx.x; e < EE; e += gridDim.x * blockDim.x) {
        int d = ei[EE + e];
        int pos = atomicAdd(&g_fill[d], 1);
        g_esrc[pos] = ei[e];
        g_ewq[pos]  = ew[e];
    }
}

// c[h] = sum_d We[h*32+d] * a_edge[h*32+d]
__global__ void cedge_kernel(const float* __restrict__ We0, const float* __restrict__ ae0,
                             const float* __restrict__ We1, const float* __restrict__ ae1) {
    const float* We = blockIdx.x ? We1 : We0;
    const float* ae = blockIdx.x ? ae1 : ae0;
    int t = threadIdx.x;
    float p = We[t] * ae[t];
    #pragma unroll
    for (int o = 16; o; o >>= 1) p += __shfl_xor_sync(~0u, p, o);
    if ((t & 31) == 0) g_cedge[blockIdx.x][t >> 5] = p;
}

// ---------------- fused GroupNorm + LeakyReLU + GEMM + scores -------------
__global__ void __launch_bounds__(128) gemm_kernel(
    const float* __restrict__ x, const float* __restrict__ gamma, const float* __restrict__ beta,
    const float* __restrict__ W, const float* __restrict__ a_src, const float* __restrict__ a_dst,
    float* __restrict__ hout, float* __restrict__ ssrc, float* __restrict__ sdst)
{
    extern __shared__ float sh[];
    float* Wsh = sh;            // 128*128
    float* xs  = sh + 16384;    // 32*128
    int t = threadIdx.x, w = t >> 5, l = t & 31;
    int row0 = blockIdx.x * 32;

    for (int i = t; i < 16384; i += 128) Wsh[i] = W[i];

    float4 gmm = reinterpret_cast<const float4*>(gamma)[l];
    float4 bt  = reinterpret_cast<const float4*>(beta)[l];
    float4 a_s = reinterpret_cast<const float4*>(a_src)[l];
    float4 a_d = reinterpret_cast<const float4*>(a_dst)[l];

    #pragma unroll
    for (int j = 0; j < 8; j++) {
        int rl = w + 4 * j;
        int row = row0 + rl;
        float4 v = make_float4(0.f, 0.f, 0.f, 0.f);
        if (row < NN) v = reinterpret_cast<const float4*>(x)[row * 32 + l];
        float s1 = v.x + v.y + v.z + v.w;
        float s2 = v.x * v.x + v.y * v.y + v.z * v.z + v.w * v.w;
        s1 += __shfl_xor_sync(~0u, s1, 1, 4); s2 += __shfl_xor_sync(~0u, s2, 1, 4);
        s1 += __shfl_xor_sync(~0u, s1, 2, 4); s2 += __shfl_xor_sync(~0u, s2, 2, 4);
        float mu  = s1 * (1.f / 16.f);
        float var = s2 * (1.f / 16.f) - mu * mu;
        float rs  = rsqrtf(var + 1e-5f);
        float4 xn;
        xn.x = (v.x - mu) * rs * gmm.x + bt.x;
        xn.y = (v.y - mu) * rs * gmm.y + bt.y;
        xn.z = (v.z - mu) * rs * gmm.z + bt.z;
        xn.w = (v.w - mu) * rs * gmm.w + bt.w;
        xn.x = fmaxf(xn.x, 0.01f * xn.x);
        xn.y = fmaxf(xn.y, 0.01f * xn.y);
        xn.z = fmaxf(xn.z, 0.01f * xn.z);
        xn.w = fmaxf(xn.w, 0.01f * xn.w);
        reinterpret_cast<float4*>(xs)[rl * 32 + l] = xn;
    }
    __syncthreads();

    float4 acc[8];
    #pragma unroll
    for (int j = 0; j < 8; j++) acc[j] = make_float4(0.f, 0.f, 0.f, 0.f);
    const float4* W4 = reinterpret_cast<const float4*>(Wsh);
    #pragma unroll 4
    for (int k = 0; k < 128; k++) {
        float4 wv = W4[k * 32 + l];
        #pragma unroll
        for (int j = 0; j < 8; j++) {
            float xk = xs[(w + 4 * j) * 128 + k];
            acc[j].x += wv.x * xk;
            acc[j].y += wv.y * xk;
            acc[j].z += wv.z * xk;
            acc[j].w += wv.w * xk;
        }
    }

    #pragma unroll
    for (int j = 0; j < 8; j++) {
        int row = row0 + w + 4 * j;
        if (row < NN) {
            reinterpret_cast<float4*>(hout)[row * 32 + l] = acc[j];
            float ps = acc[j].x * a_s.x + acc[j].y * a_s.y + acc[j].z * a_s.z + acc[j].w * a_s.w;
            float pd = acc[j].x * a_d.x + acc[j].y * a_d.y + acc[j].z * a_d.z + acc[j].w * a_d.w;
            ps += __shfl_xor_sync(~0u, ps, 1, 8); pd += __shfl_xor_sync(~0u, pd, 1, 8);
            ps += __shfl_xor_sync(~0u, ps, 2, 8); pd += __shfl_xor_sync(~0u, pd, 2, 8);
            ps += __shfl_xor_sync(~0u, ps, 4, 8); pd += __shfl_xor_sync(~0u, pd, 4, 8);
            if ((l & 7) == 0) {
                ssrc[row * 4 + (l >> 3)] = ps;
                sdst[row * 4 + (l >> 3)] = pd;
            }
        }
    }
}

// ---------------- per-(dst, head-pair) softmax + aggregation ---------------
// One warp per (node, head-pair): halves the serial edge chain per warp and
// doubles chip-wide MLP vs one-warp-per-node. Lane l covers feature l of both
// heads in the pair (2 x 128B coalesced gathers per edge).
__global__ void __launch_bounds__(256) aggr_kernel(
    const float* __restrict__ hmat, const float* __restrict__ ssrc, const float* __restrict__ sdst,
    const float* __restrict__ bias, float* __restrict__ out, int layer)
{
    __shared__ int    sh_src[8][32];
    __shared__ float2 sh_w[8][32];
    int wid = threadIdx.x >> 5, l = threadIdx.x & 31;
    int unit = blockIdx.x * 8 + wid;
    if (unit >= 2 * NN) return;
    int n  = unit >> 1;
    int hp = unit & 1;          // head pair: heads 2hp, 2hp+1
    int fo = hp * 64;           // feature offset

    int beg = g_rowptr[n], end = g_rowptr[n + 1];
    float c0 = g_cedge[layer][2 * hp], c1 = g_cedge[layer][2 * hp + 1];
    float ewm = __int_as_float(g_ewmax_bits);
    float2 sd  = *reinterpret_cast<const float2*>(sdst + n * 4 + 2 * hp);
    float2 ssn = *reinterpret_cast<const float2*>(ssrc + n * 4 + 2 * hp);

    // self-loop logits
    float ls0 = lrelu_att(ssn.x + sd.x + ewm * c0);
    float ls1 = lrelu_att(ssn.y + sd.y + ewm * c1);

    // pass 1: per-head max over in-edges
    float M0 = ls0, M1 = ls1;
    for (int e = beg + l; e < end; e += 32) {
        int s = g_esrc[e];
        float wg = g_ewq[e];
        float2 ss = *reinterpret_cast<const float2*>(ssrc + s * 4 + 2 * hp);
        M0 = fmaxf(M0, lrelu_att(ss.x + sd.x + wg * c0));
        M1 = fmaxf(M1, lrelu_att(ss.y + sd.y + wg * c1));
    }
    #pragma unroll
    for (int o = 16; o; o >>= 1) {
        M0 = fmaxf(M0, __shfl_xor_sync(~0u, M0, o));
        M1 = fmaxf(M1, __shfl_xor_sync(~0u, M1, o));
    }

    float w0s = __expf(ls0 - M0), w1s = __expf(ls1 - M1);

    const float* hn = hmat + n * 128 + fo + l;
    float acc0 = w0s * hn[0];
    float acc1 = w1s * hn[32];
    float sum0 = 0.f, sum1 = 0.f;

    // pass 2: chunks of 32 edges; lane-parallel exp, then warp-serial feature
    // accumulation unrolled x2 (4 independent LDGs in flight per iteration)
    for (int base = beg; base < end; base += 32) {
        int e = base + l;
        if (e < end) {
            int s = g_esrc[e];
            float wg = g_ewq[e];
            float2 ss = *reinterpret_cast<const float2*>(ssrc + s * 4 + 2 * hp);
            float e0 = __expf(lrelu_att(ss.x + sd.x + wg * c0) - M0);
            float e1 = __expf(lrelu_att(ss.y + sd.y + wg * c1) - M1);
            sum0 += e0; sum1 += e1;
            sh_src[wid][l] = s;
            sh_w[wid][l] = make_float2(e0, e1);
        }
        __syncwarp();
        int cnt = end - base; if (cnt > 32) cnt = 32;
        int i = 0;
        for (; i + 2 <= cnt; i += 2) {
            int sa = sh_src[wid][i], sb = sh_src[wid][i + 1];
            float2 wa = sh_w[wid][i], wb = sh_w[wid][i + 1];
            const float* pa = hmat + sa * 128 + fo + l;
            const float* pb = hmat + sb * 128 + fo + l;
            float a0 = pa[0], a1 = pa[32];
            float b0 = pb[0], b1 = pb[32];
            acc0 += wa.x * a0; acc1 += wa.y * a1;
            acc0 += wb.x * b0; acc1 += wb.y * b1;
        }
        if (i < cnt) {
            int sa = sh_src[wid][i];
            float2 wa = sh_w[wid][i];
            const float* pa = hmat + sa * 128 + fo + l;
            acc0 += wa.x * pa[0];
            acc1 += wa.y * pa[32];
        }
        __syncwarp();
    }

    #pragma unroll
    for (int o = 16; o; o >>= 1) {
        sum0 += __shfl_xor_sync(~0u, sum0, o);
        sum1 += __shfl_xor_sync(~0u, sum1, o);
    }
    sum0 += w0s; sum1 += w1s;
    float i0 = 1.f / (sum0 + 1e-16f), i1 = 1.f / (sum1 + 1e-16f);

    float* op = out + n * 128 + fo + l;
    op[0]  = acc0 * i0 + bias[fo + l];
    op[32] = acc1 * i1 + bias[fo + 32 + l];
}

// ---------------- launch ---------------------------------------------------
extern "C" void kernel_launch(void* const* d_in, const int* in_sizes, int n_in,
                              void* d_out, int out_size) {
    const float* x  = (const float*)d_in[0];
    const int*   ei = (const int*)d_in[1];
    const float* ew = (const float*)d_in[2];
    const float* P[2][8];
    for (int L = 0; L < 2; L++)
        for (int j = 0; j < 8; j++)
            P[L][j] = (const float*)d_in[3 + L * 8 + j];
    // P[L]: 0 gamma, 1 beta, 2 W, 3 We, 4 a_src, 5 a_dst, 6 a_edge, 7 bias

    float *d_h, *d_xbuf, *d_ssrc, *d_sdst;
    cudaGetSymbolAddress((void**)&d_h,    g_h);
    cudaGetSymbolAddress((void**)&d_xbuf, g_xbuf);
    cudaGetSymbolAddress((void**)&d_ssrc, g_ssrc);
    cudaGetSymbolAddress((void**)&d_sdst, g_sdst);

    cudaFuncSetAttribute(gemm_kernel, cudaFuncAttributeMaxDynamicSharedMemorySize, 81920);

    // graph preprocessing (deterministic work every call)
    init_ewmax_kernel<<<256, 256>>>(ew);
    count_kernel<<<512, 256>>>(ei);
    scanA_kernel<<<SCAN_B, 256>>>();
    scanB_kernel<<<1, 256>>>();
    scanC_kernel<<<SCAN_B, 256>>>();
    scatter_kernel<<<512, 256>>>(ei, ew);
    cedge_kernel<<<2, 128>>>(P[0][3], P[0][6], P[1][3], P[1][6]);

    const int gemm_blocks = (NN + 31) / 32;
    const int aggr_blocks = (2 * NN + 7) / 8;

    // layer 0
    gemm_kernel<<<gemm_blocks, 128, 81920>>>(x, P[0][0], P[0][1], P[0][2], P[0][4], P[0][5],
                                             d_h, d_ssrc, d_sdst);
    aggr_kernel<<<aggr_blocks, 256>>>(d_h, d_ssrc, d_sdst, P[0][7], d_xbuf, 0);

    // layer 1
    gemm_kernel<<<gemm_blocks, 128, 81920>>>(d_xbuf, P[1][0], P[1][1], P[1][2], P[1][4], P[1][5],
                                             d_h, d_ssrc, d_sdst);
    aggr_kernel<<<aggr_blocks, 256>>>(d_h, d_ssrc, d_sdst, P[1][7], (float*)d_out, 1);
}